// round 5
// baseline (speedup 1.0000x reference)
#include <cuda_runtime.h>
#include <math.h>

#define BB 4
#define TT 2048
#define DD 1024
#define DK 128
#define RR (BB*TT)   // 8192

// Scratch (device globals: allocation-free)
__device__ float g_Q[RR*DK];
__device__ float g_K[RR*DK];
__device__ float g_V[RR*DK];
__device__ float g_O[RR*DK];

// ---------------------------------------------------------------------------
// GEMM tile body: C[m0:m0+64, n0:n0+128] = A[M,K] @ B[K,N] (row-major).
// 256 threads, 4x8 register tile, BK=16, A stored transposed in smem.
// Inner loop: 3 LDS.128 per 32 FMA per thread.
// ---------------------------------------------------------------------------
#define AS_STRIDE 68

__device__ __forceinline__ void gemm_tile_64x128(
    const float* __restrict__ A, const float* __restrict__ Bw,
    float* __restrict__ C, int M, int N, int K, int m0, int n0)
{
    __shared__ float As[16 * AS_STRIDE];   // [kk][row], padded
    __shared__ float Bs[16 * 128];         // [kk][col]

    const int tid = threadIdx.x;
    const int tx = tid & 15, ty = tid >> 4;

    float acc[4][8];
#pragma unroll
    for (int r = 0; r < 4; r++)
#pragma unroll
        for (int j = 0; j < 8; j++) acc[r][j] = 0.f;

    // A tile load indices: 64 rows x 16 k = 256 float4
    const int ar = tid >> 2;                 // row 0..63
    const int akg = (tid & 3) * 4;           // k group 0,4,8,12

    for (int k0 = 0; k0 < K; k0 += 16) {
        // --- load A tile transposed ---
        float4 a = *(const float4*)&A[(size_t)(m0 + ar) * K + k0 + akg];
        As[(akg + 0) * AS_STRIDE + ar] = a.x;
        As[(akg + 1) * AS_STRIDE + ar] = a.y;
        As[(akg + 2) * AS_STRIDE + ar] = a.z;
        As[(akg + 3) * AS_STRIDE + ar] = a.w;
        // --- load B tile straight (16x128 = 512 float4, 2 per thread) ---
#pragma unroll
        for (int t = 0; t < 2; t++) {
            int idx = tid + t * 256;
            int br = idx >> 5, bc = (idx & 31) * 4;
            *(float4*)&Bs[br * 128 + bc] =
                *(const float4*)&Bw[(size_t)(k0 + br) * N + n0 + bc];
        }
        __syncthreads();

#pragma unroll
        for (int kk = 0; kk < 16; kk++) {
            float4 a4 = *(const float4*)&As[kk * AS_STRIDE + ty * 4];
            float4 b0 = *(const float4*)&Bs[kk * 128 + tx * 4];
            float4 b1 = *(const float4*)&Bs[kk * 128 + tx * 4 + 64];
            float av[4] = {a4.x, a4.y, a4.z, a4.w};
            float bv[8] = {b0.x, b0.y, b0.z, b0.w, b1.x, b1.y, b1.z, b1.w};
#pragma unroll
            for (int r = 0; r < 4; r++)
#pragma unroll
                for (int j = 0; j < 8; j++) acc[r][j] += av[r] * bv[j];
        }
        __syncthreads();
    }

#pragma unroll
    for (int r = 0; r < 4; r++) {
        size_t row = (size_t)(m0 + ty * 4 + r) * N + n0;
        float4 o0 = {acc[r][0], acc[r][1], acc[r][2], acc[r][3]};
        float4 o1 = {acc[r][4], acc[r][5], acc[r][6], acc[r][7]};
        *(float4*)&C[row + tx * 4]      = o0;
        *(float4*)&C[row + tx * 4 + 64] = o1;
    }
}

// Fused QKV projection: grid (128, 1, 3), blockIdx.z selects W / output.
__global__ __launch_bounds__(256) void qkv_kernel(
    const float* __restrict__ x,
    const float* __restrict__ Wq,
    const float* __restrict__ Wk,
    const float* __restrict__ Wv)
{
    const float* W;
    float* C;
    if (blockIdx.z == 0)      { W = Wq; C = g_Q; }
    else if (blockIdx.z == 1) { W = Wk; C = g_K; }
    else                      { W = Wv; C = g_V; }
    gemm_tile_64x128(x, W, C, RR, DK, DD, blockIdx.x * 64, 0);
}

// Output projection: grid (8, 128).
__global__ __launch_bounds__(256) void outproj_kernel(
    const float* __restrict__ Wo, float* __restrict__ out)
{
    gemm_tile_64x128(g_O, Wo, out, RR, DD, DK, blockIdx.y * 64, blockIdx.x * 128);
}

// ---------------------------------------------------------------------------
// Flash attention (causal), BQ=64, BKV=64, d=128, 512 threads.
// Thread layout: tx = tid&15 (S cols: tx*4..+3; O cols: tx*8..+7),
//                tyS = tid>>4 in [0,32) (rows: tyS*2 + {0,1}).
// Qs padded to stride 132, Kt (transposed K) stride 68, Ps stride 68.
// ---------------------------------------------------------------------------
#define QS_STRIDE 132
#define KT_STRIDE 68
#define PS_STRIDE 68
#define FLASH_SMEM_FLOATS (64*QS_STRIDE + 128*KT_STRIDE + 64*128 + 64*PS_STRIDE)

__global__ __launch_bounds__(512) void flash_kernel()
{
    extern __shared__ float sm[];
    float* Qs = sm;                          // 64 x 132
    float* Kt = Qs + 64 * QS_STRIDE;         // 128 x 68 (Kt[d][c])
    float* Vs = Kt + 128 * KT_STRIDE;        // 64 x 128
    float* Ps = Vs + 64 * 128;               // 64 x 68

    const int tid = threadIdx.x;
    const int tx = tid & 15;
    const int tyS = tid >> 4;                // 0..31
    const int row0 = tyS * 2;
    const int qt = blockIdx.x;
    const int b  = blockIdx.y;
    const int q0 = qt * 64;

    const float* Qg = g_Q + (size_t)(b * TT + q0) * DK;
    const float* Kg = g_K + (size_t)b * TT * DK;
    const float* Vg = g_V + (size_t)b * TT * DK;

    // Load Q tile (coalesced, padded stride)
#pragma unroll
    for (int i = 0; i < 16; i++) {
        int e = i * 512 + tid;
        Qs[(e >> 7) * QS_STRIDE + (e & 127)] = Qg[e];
    }

    float m[2], l[2], acc[2][8];
#pragma unroll
    for (int r = 0; r < 2; r++) { m[r] = -1e30f; l[r] = 0.f; }
#pragma unroll
    for (int r = 0; r < 2; r++)
#pragma unroll
        for (int j = 0; j < 8; j++) acc[r][j] = 0.f;

    const float scale = 0.08838834764831845f;   // 1/sqrt(128)

    // K transpose-load indices: c = tid&63, d block = (tid>>6)*16
    const int kc = tid & 63;
    const int kd0 = (tid >> 6) * 16;

    for (int j = 0; j <= qt; j++) {
        __syncthreads();   // prev iter's Kt/Vs reads complete

        const float* Kj = Kg + (size_t)j * 64 * DK;
        const float* Vj = Vg + (size_t)j * 64 * DK;
        // K transposed: thread reads 64B contiguous of row kc, scatters
        // conflict-free (banks = c within warp).
#pragma unroll
        for (int t = 0; t < 4; t++) {
            float4 kf = *(const float4*)&Kj[(size_t)kc * DK + kd0 + t * 4];
            int d = kd0 + t * 4;
            Kt[(d + 0) * KT_STRIDE + kc] = kf.x;
            Kt[(d + 1) * KT_STRIDE + kc] = kf.y;
            Kt[(d + 2) * KT_STRIDE + kc] = kf.z;
            Kt[(d + 3) * KT_STRIDE + kc] = kf.w;
        }
        // V straight (coalesced)
#pragma unroll
        for (int i = 0; i < 16; i++) {
            int e = i * 512 + tid;
            Vs[e] = Vj[e];
        }
        __syncthreads();

        // --- S = Q K^T (2 rows x 4 cols per thread) ---
        float S[2][4];
#pragma unroll
        for (int r = 0; r < 2; r++)
#pragma unroll
            for (int cc = 0; cc < 4; cc++) S[r][cc] = 0.f;

#pragma unroll 4
        for (int d0 = 0; d0 < 128; d0 += 4) {
            float4 kv[4];
#pragma unroll
            for (int t = 0; t < 4; t++)
                kv[t] = *(const float4*)&Kt[(d0 + t) * KT_STRIDE + tx * 4];
#pragma unroll
            for (int r = 0; r < 2; r++) {
                float4 q4 = *(const float4*)&Qs[(row0 + r) * QS_STRIDE + d0];
                S[r][0] += q4.x*kv[0].x + q4.y*kv[1].x + q4.z*kv[2].x + q4.w*kv[3].x;
                S[r][1] += q4.x*kv[0].y + q4.y*kv[1].y + q4.z*kv[2].y + q4.w*kv[3].y;
                S[r][2] += q4.x*kv[0].z + q4.y*kv[1].z + q4.z*kv[2].z + q4.w*kv[3].z;
                S[r][3] += q4.x*kv[0].w + q4.y*kv[1].w + q4.z*kv[2].w + q4.w*kv[3].w;
            }
        }

#pragma unroll
        for (int r = 0; r < 2; r++)
#pragma unroll
            for (int cc = 0; cc < 4; cc++) S[r][cc] *= scale;

        if (j == qt) {   // causal mask only on diagonal tile
#pragma unroll
            for (int r = 0; r < 2; r++) {
                int row = q0 + row0 + r;
#pragma unroll
                for (int cc = 0; cc < 4; cc++) {
                    int col = j * 64 + tx * 4 + cc;
                    if (col > row) S[r][cc] = -1e30f;
                }
            }
        }

        // --- online softmax (row spread over 16 tx lanes) ---
#pragma unroll
        for (int r = 0; r < 2; r++) {
            float mt = fmaxf(fmaxf(S[r][0], S[r][1]), fmaxf(S[r][2], S[r][3]));
#pragma unroll
            for (int off = 1; off < 16; off <<= 1)
                mt = fmaxf(mt, __shfl_xor_sync(0xffffffffu, mt, off));
            float mn = fmaxf(m[r], mt);
            float alpha = __expf(m[r] - mn);
            float p0 = __expf(S[r][0] - mn);
            float p1 = __expf(S[r][1] - mn);
            float p2 = __expf(S[r][2] - mn);
            float p3 = __expf(S[r][3] - mn);
            float lt = (p0 + p1) + (p2 + p3);
#pragma unroll
            for (int off = 1; off < 16; off <<= 1)
                lt += __shfl_xor_sync(0xffffffffu, lt, off);
            l[r] = l[r] * alpha + lt;
            m[r] = mn;
#pragma unroll
            for (int jj = 0; jj < 8; jj++) acc[r][jj] *= alpha;
            float4 pv = {p0, p1, p2, p3};
            *(float4*)&Ps[(row0 + r) * PS_STRIDE + tx * 4] = pv;
        }
        __syncwarp();   // Ps producer/consumer are the same half-warp

        // --- O += P V (float4 V loads, cols tx*8..+7) ---
#pragma unroll 4
        for (int c = 0; c < 64; c++) {
            float p0 = Ps[(row0 + 0) * PS_STRIDE + c];
            float p1 = Ps[(row0 + 1) * PS_STRIDE + c];
            float4 v0 = *(const float4*)&Vs[c * 128 + tx * 8];
            float4 v1 = *(const float4*)&Vs[c * 128 + tx * 8 + 4];
            acc[0][0] += p0 * v0.x; acc[0][1] += p0 * v0.y;
            acc[0][2] += p0 * v0.z; acc[0][3] += p0 * v0.w;
            acc[0][4] += p0 * v1.x; acc[0][5] += p0 * v1.y;
            acc[0][6] += p0 * v1.z; acc[0][7] += p0 * v1.w;
            acc[1][0] += p1 * v0.x; acc[1][1] += p1 * v0.y;
            acc[1][2] += p1 * v0.z; acc[1][3] += p1 * v0.w;
            acc[1][4] += p1 * v1.x; acc[1][5] += p1 * v1.y;
            acc[1][6] += p1 * v1.z; acc[1][7] += p1 * v1.w;
        }
    }

    // epilogue: normalize and store O (float4)
#pragma unroll
    for (int r = 0; r < 2; r++) {
        float inv = 1.f / l[r];
        size_t row = (size_t)(b * TT + q0 + row0 + r) * DK;
        float4 o0 = {acc[r][0]*inv, acc[r][1]*inv, acc[r][2]*inv, acc[r][3]*inv};
        float4 o1 = {acc[r][4]*inv, acc[r][5]*inv, acc[r][6]*inv, acc[r][7]*inv};
        *(float4*)&g_O[row + tx * 8]     = o0;
        *(float4*)&g_O[row + tx * 8 + 4] = o1;
    }
}

// ---------------------------------------------------------------------------
extern "C" void kernel_launch(void* const* d_in, const int* in_sizes, int n_in,
                              void* d_out, int out_size)
{
    const float* x  = (const float*)d_in[0];
    const float* Wq = (const float*)d_in[1];
    const float* Wk = (const float*)d_in[2];
    const float* Wv = (const float*)d_in[3];
    const float* Wo = (const float*)d_in[4];
    float* out = (float*)d_out;

    const int flash_smem = FLASH_SMEM_FLOATS * (int)sizeof(float);
    cudaFuncSetAttribute(flash_kernel,
                         cudaFuncAttributeMaxDynamicSharedMemorySize, flash_smem);

    // Fused QKV projections: [8192,1024] @ [1024,128] x3 in one launch
    qkv_kernel<<<dim3(RR / 64, 1, 3), 256>>>(x, Wq, Wk, Wv);

    // Causal flash attention
    flash_kernel<<<dim3(TT / 64, BB), 512, flash_smem>>>();

    // Output projection: [8192,128] @ [128,1024]
    outproj_kernel<<<dim3(DD / 128, RR / 64), 256>>>(Wo, out);
}

// round 6
// speedup vs baseline: 4.0994x; 4.0994x over previous
#include <cuda_runtime.h>
#include <math.h>

#define BB 4
#define TT 2048
#define DD 1024
#define DK 128
#define RR (BB*TT)   // 8192

#define BPB 40              // flash blocks per batch (chunked schedule)
#define NSLOT (BB*BPB)      // 160 partial slots

// Scratch (device globals: allocation-free)
__device__ float g_Q[RR*DK];
__device__ float g_K[RR*DK];
__device__ float g_V[RR*DK];
__device__ float g_O[RR*DK];
__device__ float g_pO[(size_t)NSLOT*128*DK];   // partial O per chunk slot
__device__ float g_pml[NSLOT*128*2];           // partial (m,l) per row

__device__ __forceinline__ unsigned f2tf(float f) {
    unsigned u; asm("cvt.rna.tf32.f32 %0, %1;" : "=r"(u) : "f"(f)); return u;
}

__device__ __forceinline__ void mma_tf32(float c[4],
    unsigned a0, unsigned a1, unsigned a2, unsigned a3,
    unsigned b0, unsigned b1)
{
    asm volatile(
        "mma.sync.aligned.m16n8k8.row.col.f32.tf32.tf32.f32 "
        "{%0,%1,%2,%3}, {%4,%5,%6,%7}, {%8,%9}, {%0,%1,%2,%3};"
        : "+f"(c[0]), "+f"(c[1]), "+f"(c[2]), "+f"(c[3])
        : "r"(a0), "r"(a1), "r"(a2), "r"(a3), "r"(b0), "r"(b1));
}

// ---------------------------------------------------------------------------
// tf32 GEMM: C[128 x 128 tile] = A[M,K] @ B[K,N], row-major fp32 in/out.
// 256 threads = 8 warps as 2(m) x 4(n); warp tile 64x32; BK=32.
// As stored transposed [k][m], Bs [k][n], both stride 136 (== 8 mod 32):
// fragment LDS bank = (8*(lane&3) + (lane>>2)) -> conflict-free.
// ---------------------------------------------------------------------------
#define GST 136

__device__ __forceinline__ void gemm128_tf32(
    const float* __restrict__ A, const float* __restrict__ Bw,
    float* __restrict__ C, int N, int K, int m0, int n0)
{
    __shared__ unsigned As[32 * GST];
    __shared__ unsigned Bs[32 * GST];

    const int tid = threadIdx.x, lane = tid & 31, w = tid >> 5;
    const int wm = (w >> 2) * 64, wn = (w & 3) * 32;
    const int g = lane >> 2, c = lane & 3;

    float acc[4][4][4];
#pragma unroll
    for (int mf = 0; mf < 4; mf++)
#pragma unroll
        for (int nf = 0; nf < 4; nf++)
#pragma unroll
            for (int j = 0; j < 4; j++) acc[mf][nf][j] = 0.f;

    const int arow = tid >> 1, acol = (tid & 1) * 16;   // A: 128 rows x 32 k
    const int brow = tid >> 3, bcol = (tid & 7) * 4;    // B: 32 k x 128 n

    for (int k0 = 0; k0 < K; k0 += 32) {
        // stage A (transposed, tf32)
#pragma unroll
        for (int i = 0; i < 4; i++) {
            float4 v = *(const float4*)&A[(size_t)(m0 + arow) * K + k0 + acol + i * 4];
            int kk = acol + i * 4;
            As[(kk + 0) * GST + arow] = f2tf(v.x);
            As[(kk + 1) * GST + arow] = f2tf(v.y);
            As[(kk + 2) * GST + arow] = f2tf(v.z);
            As[(kk + 3) * GST + arow] = f2tf(v.w);
        }
        // stage B (straight, tf32)
#pragma unroll
        for (int i = 0; i < 4; i++) {
            float4 v = *(const float4*)&Bw[(size_t)(k0 + brow) * N + n0 + bcol + i * 32];
            uint4 u = {f2tf(v.x), f2tf(v.y), f2tf(v.z), f2tf(v.w)};
            *(uint4*)&Bs[brow * GST + bcol + i * 32] = u;
        }
        __syncthreads();

#pragma unroll
        for (int ks = 0; ks < 4; ks++) {
            const int kk = ks * 8 + c;
            unsigned a[4][4], b[4][2];
#pragma unroll
            for (int mf = 0; mf < 4; mf++) {
                int r = wm + mf * 16 + g;
                a[mf][0] = As[kk * GST + r];
                a[mf][1] = As[kk * GST + r + 8];
                a[mf][2] = As[(kk + 4) * GST + r];
                a[mf][3] = As[(kk + 4) * GST + r + 8];
            }
#pragma unroll
            for (int nf = 0; nf < 4; nf++) {
                int n = wn + nf * 8 + g;
                b[nf][0] = Bs[kk * GST + n];
                b[nf][1] = Bs[(kk + 4) * GST + n];
            }
#pragma unroll
            for (int mf = 0; mf < 4; mf++)
#pragma unroll
                for (int nf = 0; nf < 4; nf++)
                    mma_tf32(acc[mf][nf], a[mf][0], a[mf][1], a[mf][2], a[mf][3],
                             b[nf][0], b[nf][1]);
        }
        __syncthreads();
    }

    // epilogue
#pragma unroll
    for (int mf = 0; mf < 4; mf++)
#pragma unroll
        for (int nf = 0; nf < 4; nf++) {
            size_t r0 = (size_t)(m0 + wm + mf * 16 + g) * N + n0 + wn + nf * 8 + 2 * c;
            float2 lo = {acc[mf][nf][0], acc[mf][nf][1]};
            float2 hi = {acc[mf][nf][2], acc[mf][nf][3]};
            *(float2*)&C[r0]               = lo;
            *(float2*)&C[r0 + (size_t)8 * N] = hi;
        }
}

__global__ __launch_bounds__(256, 2) void qkv_kernel(
    const float* __restrict__ x, const float* __restrict__ Wq,
    const float* __restrict__ Wk, const float* __restrict__ Wv)
{
    const float* W; float* C;
    if (blockIdx.z == 0)      { W = Wq; C = g_Q; }
    else if (blockIdx.z == 1) { W = Wk; C = g_K; }
    else                      { W = Wv; C = g_V; }
    gemm128_tf32(x, W, C, DK, DD, blockIdx.x * 128, 0);
}

__global__ __launch_bounds__(256, 2) void outproj_kernel(
    const float* __restrict__ Wo, float* __restrict__ out)
{
    gemm128_tf32(g_O, Wo, out, DD, DK, blockIdx.y * 128, blockIdx.x * 128);
}

// ---------------------------------------------------------------------------
// Flash attention, tf32 mma, split-KV.
// BQ=128, BKV=64, 256 threads = 8 warps; warp owns 16 q-rows (all 64 S cols,
// all 128 O cols). Chunk = up to 8 KV tiles; partial (O,m,l) -> g_pO/g_pml.
// Smem strides: Qs/Ks 132 (==4 mod 32), Vs 136 (==8), Ps 68 (==4) — all
// fragment LDS conflict-free for their respective index shapes.
// ---------------------------------------------------------------------------
#define QSS 132
#define KSS 132
#define VSS 136
#define PSS 68
#define OFF_K (128*QSS)
#define OFF_V (OFF_K + 64*KSS)
#define OFF_P (OFF_V + 64*VSS)
#define FLASH_SMEM ((OFF_P + 128*PSS) * 4)   // 171008 bytes

__global__ __launch_bounds__(256, 1) void flash_kernel()
{
    extern __shared__ unsigned sm[];
    unsigned* Qs = sm;
    unsigned* Ks = sm + OFF_K;
    unsigned* Vs = sm + OFF_V;
    unsigned* Ps = sm + OFF_P;

    const int tid = threadIdx.x, lane = tid & 31, w = tid >> 5;
    const int g = lane >> 2, c = lane & 3;
    const int wm = w * 16;

    // ---- schedule decode: reversed order puts big (qt) chunks first ----
    const int b  = blockIdx.x / BPB;
    const int wr = BPB - 1 - (blockIdx.x % BPB);
    int qt = 0, chunk = 0, prefix = 0;
    {
        int accn = 0;
        for (int q = 0; q < 16; q++) {
            int n = q / 4 + 1;                 // chunks for q-tile q
            if (wr < accn + n) { qt = q; chunk = wr - accn; prefix = accn; break; }
            accn += n;
        }
    }
    const int slot = b * BPB + prefix + chunk;
    const int q0 = qt * 128;
    const int it_total = 2 * qt + 2;
    const int t0 = chunk * 8;
    const int tlen = (it_total - t0 < 8) ? (it_total - t0) : 8;

    const float* Qg = g_Q + ((size_t)b * TT + q0) * DK;
    const float* Kg = g_K + (size_t)b * TT * DK;
    const float* Vg = g_V + (size_t)b * TT * DK;

    // load Q tile (tf32)
#pragma unroll
    for (int i = 0; i < 16; i++) {
        int idx = i * 256 + tid, r = idx >> 5, c4 = idx & 31;
        float4 v = *(const float4*)&Qg[r * 128 + c4 * 4];
        uint4 u = {f2tf(v.x), f2tf(v.y), f2tf(v.z), f2tf(v.w)};
        *(uint4*)&Qs[r * QSS + c4 * 4] = u;
    }

    float mr0 = -1e30f, mr1 = -1e30f, l0 = 0.f, l1 = 0.f;
    float O[16][4];
#pragma unroll
    for (int nf = 0; nf < 16; nf++)
#pragma unroll
        for (int j = 0; j < 4; j++) O[nf][j] = 0.f;

    const float scale = 0.08838834764831845f;   // 1/sqrt(128)

    for (int ti = 0; ti < tlen; ti++) {
        const int t = t0 + ti;
        __syncthreads();
        const float* Kj = Kg + (size_t)t * 64 * DK;
        const float* Vj = Vg + (size_t)t * 64 * DK;
#pragma unroll
        for (int i = 0; i < 8; i++) {
            int idx = i * 256 + tid, r = idx >> 5, c4 = idx & 31;
            float4 kv = *(const float4*)&Kj[r * 128 + c4 * 4];
            uint4 uk = {f2tf(kv.x), f2tf(kv.y), f2tf(kv.z), f2tf(kv.w)};
            *(uint4*)&Ks[r * KSS + c4 * 4] = uk;
            float4 vv = *(const float4*)&Vj[r * 128 + c4 * 4];
            uint4 uv = {f2tf(vv.x), f2tf(vv.y), f2tf(vv.z), f2tf(vv.w)};
            *(uint4*)&Vs[r * VSS + c4 * 4] = uv;
        }
        __syncthreads();

        // --- S = Q K^T : warp 16x64, 8 n-frags ---
        float s[8][4];
#pragma unroll
        for (int nf = 0; nf < 8; nf++)
#pragma unroll
            for (int j = 0; j < 4; j++) s[nf][j] = 0.f;

#pragma unroll
        for (int ks = 0; ks < 16; ks++) {
            const int kk = ks * 8 + c;
            unsigned a0 = Qs[(wm + g) * QSS + kk];
            unsigned a1 = Qs[(wm + g + 8) * QSS + kk];
            unsigned a2 = Qs[(wm + g) * QSS + kk + 4];
            unsigned a3 = Qs[(wm + g + 8) * QSS + kk + 4];
#pragma unroll
            for (int nf = 0; nf < 8; nf++) {
                int n = nf * 8 + g;
                mma_tf32(s[nf], a0, a1, a2, a3,
                         Ks[n * KSS + kk], Ks[n * KSS + kk + 4]);
            }
        }

        // scale + causal mask
#pragma unroll
        for (int nf = 0; nf < 8; nf++)
#pragma unroll
            for (int j = 0; j < 4; j++) s[nf][j] *= scale;

        if (t * 64 + 63 > q0 + wm) {
            const int r0g = q0 + wm + g, r1g = r0g + 8;
#pragma unroll
            for (int nf = 0; nf < 8; nf++) {
                int col = t * 64 + nf * 8 + 2 * c;
                if (col     > r0g) s[nf][0] = -1e30f;
                if (col + 1 > r0g) s[nf][1] = -1e30f;
                if (col     > r1g) s[nf][2] = -1e30f;
                if (col + 1 > r1g) s[nf][3] = -1e30f;
            }
        }

        // --- online softmax (rows wm+g, wm+g+8; reduce over 4-lane quad) ---
        float rm0 = -1e30f, rm1 = -1e30f;
#pragma unroll
        for (int nf = 0; nf < 8; nf++) {
            rm0 = fmaxf(rm0, fmaxf(s[nf][0], s[nf][1]));
            rm1 = fmaxf(rm1, fmaxf(s[nf][2], s[nf][3]));
        }
        rm0 = fmaxf(rm0, __shfl_xor_sync(0xffffffffu, rm0, 1));
        rm0 = fmaxf(rm0, __shfl_xor_sync(0xffffffffu, rm0, 2));
        rm1 = fmaxf(rm1, __shfl_xor_sync(0xffffffffu, rm1, 1));
        rm1 = fmaxf(rm1, __shfl_xor_sync(0xffffffffu, rm1, 2));

        float mn0 = fmaxf(mr0, rm0), mn1 = fmaxf(mr1, rm1);
        float al0 = __expf(mr0 - mn0), al1 = __expf(mr1 - mn1);
        float sum0 = 0.f, sum1 = 0.f;
#pragma unroll
        for (int nf = 0; nf < 8; nf++) {
            float p0 = __expf(s[nf][0] - mn0);
            float p1 = __expf(s[nf][1] - mn0);
            float p2 = __expf(s[nf][2] - mn1);
            float p3 = __expf(s[nf][3] - mn1);
            sum0 += p0 + p1; sum1 += p2 + p3;
            int col = nf * 8 + 2 * c;
            Ps[(wm + g) * PSS + col]         = f2tf(p0);
            Ps[(wm + g) * PSS + col + 1]     = f2tf(p1);
            Ps[(wm + g + 8) * PSS + col]     = f2tf(p2);
            Ps[(wm + g + 8) * PSS + col + 1] = f2tf(p3);
        }
        sum0 += __shfl_xor_sync(0xffffffffu, sum0, 1);
        sum0 += __shfl_xor_sync(0xffffffffu, sum0, 2);
        sum1 += __shfl_xor_sync(0xffffffffu, sum1, 1);
        sum1 += __shfl_xor_sync(0xffffffffu, sum1, 2);

        l0 = l0 * al0 + sum0; l1 = l1 * al1 + sum1;
        mr0 = mn0; mr1 = mn1;
#pragma unroll
        for (int nf = 0; nf < 16; nf++) {
            O[nf][0] *= al0; O[nf][1] *= al0;
            O[nf][2] *= al1; O[nf][3] *= al1;
        }
        __syncwarp();

        // --- O += P V : warp 16x128, 16 n-frags, 8 k-slices ---
#pragma unroll
        for (int ks = 0; ks < 8; ks++) {
            const int kk = ks * 8 + c;
            unsigned a0 = Ps[(wm + g) * PSS + kk];
            unsigned a1 = Ps[(wm + g + 8) * PSS + kk];
            unsigned a2 = Ps[(wm + g) * PSS + kk + 4];
            unsigned a3 = Ps[(wm + g + 8) * PSS + kk + 4];
#pragma unroll
            for (int nf = 0; nf < 16; nf++) {
                int n = nf * 8 + g;
                mma_tf32(O[nf], a0, a1, a2, a3,
                         Vs[kk * VSS + n], Vs[(kk + 4) * VSS + n]);
            }
        }
    }

    // ---- write partial (unnormalized O, m, l) ----
    float* pO = g_pO + (size_t)slot * 128 * DK;
#pragma unroll
    for (int nf = 0; nf < 16; nf++) {
        int col = nf * 8 + 2 * c;
        float2 lo = {O[nf][0], O[nf][1]};
        float2 hi = {O[nf][2], O[nf][3]};
        *(float2*)&pO[(wm + g) * DK + col]     = lo;
        *(float2*)&pO[(wm + g + 8) * DK + col] = hi;
    }
    if (c == 0) {
        float* ml = g_pml + slot * 256;
        ml[(wm + g) * 2]         = mr0;
        ml[(wm + g) * 2 + 1]     = l0;
        ml[(wm + g + 8) * 2]     = mr1;
        ml[(wm + g + 8) * 2 + 1] = l1;
    }
}

// ---------------------------------------------------------------------------
// Combine partial chunks -> g_O (normalized). Grid 64 = (b,qt), 256 threads.
// ---------------------------------------------------------------------------
__global__ __launch_bounds__(256) void combine_kernel()
{
    const int b = blockIdx.x >> 4, qt = blockIdx.x & 15;
    const int nch = qt / 4 + 1;
    int prefix = 0;
    for (int q = 0; q < qt; q++) prefix += q / 4 + 1;
    const int base = b * BPB + prefix;

    const int row = threadIdx.x >> 1;
    const int ch0 = (threadIdx.x & 1) * 64;

    float mv[4], lv[4], wgt[4];
    float M = -1e30f;
    for (int i = 0; i < nch; i++) {
        mv[i] = g_pml[(base + i) * 256 + row * 2];
        lv[i] = g_pml[(base + i) * 256 + row * 2 + 1];
        M = fmaxf(M, mv[i]);
    }
    float L = 0.f;
    for (int i = 0; i < nch; i++) { wgt[i] = __expf(mv[i] - M); L += wgt[i] * lv[i]; }
    const float invL = 1.f / L;

    const size_t orow = ((size_t)b * TT + qt * 128 + row) * DK;
#pragma unroll 4
    for (int j = 0; j < 64; j += 4) {
        float4 a = {0.f, 0.f, 0.f, 0.f};
        for (int i = 0; i < nch; i++) {
            float4 v = *(const float4*)&g_pO[((size_t)(base + i) * 128 + row) * DK + ch0 + j];
            a.x += wgt[i] * v.x; a.y += wgt[i] * v.y;
            a.z += wgt[i] * v.z; a.w += wgt[i] * v.w;
        }
        a.x *= invL; a.y *= invL; a.z *= invL; a.w *= invL;
        *(float4*)&g_O[orow + ch0 + j] = a;
    }
}

// ---------------------------------------------------------------------------
extern "C" void kernel_launch(void* const* d_in, const int* in_sizes, int n_in,
                              void* d_out, int out_size)
{
    const float* x  = (const float*)d_in[0];
    const float* Wq = (const float*)d_in[1];
    const float* Wk = (const float*)d_in[2];
    const float* Wv = (const float*)d_in[3];
    const float* Wo = (const float*)d_in[4];
    float* out = (float*)d_out;

    cudaFuncSetAttribute(flash_kernel,
                         cudaFuncAttributeMaxDynamicSharedMemorySize, FLASH_SMEM);

    // QKV projections (tf32 tensor cores): [8192,1024] @ [1024,128] x3
    qkv_kernel<<<dim3(RR / 128, 1, 3), 256>>>(x, Wq, Wk, Wv);

    // Split-KV causal flash attention (tf32 tensor cores)
    flash_kernel<<<NSLOT, 256, FLASH_SMEM>>>();

    // Merge partial softmax chunks
    combine_kernel<<<BB * 16, 256>>>();

    // Output projection: [8192,128] @ [128,1024]
    outproj_kernel<<<dim3(DD / 128, RR / 128), 256>>>(Wo, out);
}